// round 8
// baseline (speedup 1.0000x reference)
#include <cuda_runtime.h>
#include <cstdint>
#include <cstddef>

#define B_   16
#define N_   4096
#define M_   1024
#define C1_  256
#define C2_  256
#define CO_  256

// GEMM tile: 128co x 128n per block, 512 threads, warp tile 32x32
#define TM 128
#define TN 128
#define KC 32
#define ROWBI 80              // bytes per smem row (32 int8 data + 48 pad)
#define AHL   10240           // 128 rows * 80B (one hi/lo half)
#define ASTG  20480
#define BBASE 40960
#define BHL   10240
#define BSTG  20480
#define SMEMI 81920

// ---------------- scratch (device globals) ------------------------------------
__device__ float g_interp[(size_t)B_ * C2_ * N_];
__device__ float g_h1[(size_t)B_ * CO_ * N_];
__device__ float g_h2[(size_t)B_ * CO_ * N_];
__device__ int   g_idx[(size_t)B_ * 3 * N_];
__device__ float g_w[(size_t)B_ * 3 * N_];
__device__ float g_pd[(size_t)B_ * 4 * 3 * N_];
__device__ int   g_pi[(size_t)B_ * 4 * 3 * N_];
__device__ float g_sum1[CO_], g_sq1[CO_], g_scale1[CO_], g_shift1[CO_];
__device__ float g_sum2[CO_], g_sq2[CO_], g_scale2[CO_], g_shift2[CO_];
// int8 weight images: [chunk][hl][256 co][80B], per-row scales
__device__ int8_t g_w1q[16 * 2 * 256 * ROWBI];
__device__ int8_t g_w2q[8 * 2 * 256 * ROWBI];
__device__ float  g_swr1[CO_], g_swr2[CO_];
// quantizer scales
__device__ uint32_t g_maxX1bits;          // maxabs(X1) as raw float bits (>=0 monotone)
__device__ float    g_maxX2;              // set by finalize<0>
__device__ uint32_t g_h1maxE[CO_], g_h1minE[CO_]; // encoded per-channel h1 range

// ---------------- helpers ------------------------------------------------------
__device__ __forceinline__ uint32_t smem_u32(const void* p) {
    uint32_t a;
    asm("{ .reg .u64 t; cvta.to.shared.u64 t, %1; cvt.u32.u64 %0, t; }" : "=r"(a) : "l"(p));
    return a;
}
#define CP_ASYNC16(dst, src) \
    asm volatile("cp.async.cg.shared.global [%0], [%1], 16;" :: "r"(dst), "l"(src))
#define CP_COMMIT() asm volatile("cp.async.commit_group;")
#define CP_WAIT0()  asm volatile("cp.async.wait_group 0;")

__device__ __forceinline__ void imma16832(int c[4], const uint32_t a[4], const uint32_t b[2]) {
    asm volatile(
        "mma.sync.aligned.m16n8k32.row.col.s32.s8.s8.s32 "
        "{%0,%1,%2,%3}, {%4,%5,%6,%7}, {%8,%9}, {%0,%1,%2,%3};"
        : "+r"(c[0]), "+r"(c[1]), "+r"(c[2]), "+r"(c[3])
        : "r"(a[0]), "r"(a[1]), "r"(a[2]), "r"(a[3]), "r"(b[0]), "r"(b[1]));
}
__device__ __forceinline__ void ldmx4(uint32_t r[4], uint32_t addr) {
    asm volatile("ldmatrix.sync.aligned.m8n8.x4.shared.b16 {%0,%1,%2,%3}, [%4];"
                 : "=r"(r[0]), "=r"(r[1]), "=r"(r[2]), "=r"(r[3]) : "r"(addr));
}
__device__ __forceinline__ uint32_t encf(float f) {
    uint32_t u = __float_as_uint(f);
    return (u & 0x80000000u) ? ~u : (u | 0x80000000u);
}
__device__ __forceinline__ float decf(uint32_t e) {
    return (e & 0x80000000u) ? __uint_as_float(e & 0x7FFFFFFFu) : __uint_as_float(~e);
}

// ---------------- weight int8 quantization (+global init) -----------------------
__global__ void __launch_bounds__(128) wquant_kernel(const float* __restrict__ W, int Kdim,
                                                     int8_t* __restrict__ img,
                                                     float* __restrict__ swr, int do_init) {
    int co = blockIdx.x, t = threadIdx.x;
    if (do_init && co == 0) {
        for (int c = t; c < CO_; c += 128) {
            g_sum1[c] = 0.f; g_sq1[c] = 0.f; g_sum2[c] = 0.f; g_sq2[c] = 0.f;
            g_h1maxE[c] = encf(-3.4e38f);
            g_h1minE[c] = encf(3.4e38f);
        }
        if (t == 0) g_maxX1bits = 0u;
    }
    // row max
    float m = 0.f;
    for (int k = t; k < Kdim; k += 128) m = fmaxf(m, fabsf(W[(size_t)co * Kdim + k]));
    #pragma unroll
    for (int o = 16; o > 0; o >>= 1) m = fmaxf(m, __shfl_xor_sync(0xffffffffu, m, o));
    __shared__ float red[4];
    if ((t & 31) == 0) red[t >> 5] = m;
    __syncthreads();
    float mx = fmaxf(fmaxf(red[0], red[1]), fmaxf(red[2], red[3]));
    mx = fmaxf(mx, 1e-30f);
    if (t == 0) swr[co] = mx * (1.f / 126.f);
    float inv = 126.f / mx;
    for (int k = t; k < Kdim; k += 128) {
        float x = W[(size_t)co * Kdim + k] * inv;
        int ih = __float2int_rn(x);
        int il = __float2int_rn((x - (float)ih) * 128.f);
        int chunk = k >> 5, kk = k & 31;
        img[((size_t)(chunk * 2 + 0) * 256 + co) * ROWBI + kk] = (int8_t)ih;
        img[((size_t)(chunk * 2 + 1) * 256 + co) * ROWBI + kk] = (int8_t)il;
    }
    // zero pads (bytes 32..79 of every row of this co)
    int npad = (Kdim / 32) * 2 * 48;
    for (int idx = t; idx < npad; idx += 128) {
        int chunk = idx / 96, r = idx % 96;
        int hl = r / 48, pb = 32 + (r % 48);
        img[((size_t)(chunk * 2 + hl) * 256 + co) * ROWBI + pb] = 0;
    }
}

// ---------------- maxabs reduce for X1 ------------------------------------------
__global__ void __launch_bounds__(256) maxabs_kernel(const float* __restrict__ p, int n4) {
    float m = 0.f;
    for (int i = blockIdx.x * blockDim.x + threadIdx.x; i < n4; i += gridDim.x * blockDim.x) {
        float4 v = ((const float4*)p)[i];
        m = fmaxf(m, fmaxf(fmaxf(fabsf(v.x), fabsf(v.y)), fmaxf(fabsf(v.z), fabsf(v.w))));
    }
    #pragma unroll
    for (int o = 16; o > 0; o >>= 1) m = fmaxf(m, __shfl_xor_sync(0xffffffffu, m, o));
    if ((threadIdx.x & 31) == 0) atomicMax(&g_maxX1bits, __float_as_uint(m));
}

// ---------------- chunked three_nn ----------------------------------------------
__global__ void __launch_bounds__(128) knn_part_kernel(
    const float* __restrict__ unknown, const float* __restrict__ known) {
    __shared__ float4 sk[256];
    int b = blockIdx.z, ch = blockIdx.y;
    const float* kb = known + ((size_t)b * M_ + ch * 256) * 3;
    for (int j = threadIdx.x; j < 256; j += 128)
        sk[j] = make_float4(kb[j * 3 + 0], kb[j * 3 + 1], kb[j * 3 + 2], 0.f);
    __syncthreads();

    int i = blockIdx.x * 128 + threadIdx.x;
    const float* up = unknown + ((size_t)b * N_ + i) * 3;
    float px = up[0], py = up[1], pz = up[2];
    float bd0 = 1e30f, bd1 = 1e30f, bd2 = 1e30f;
    int   bi0 = 0, bi1 = 0, bi2 = 0;
    #pragma unroll 4
    for (int j = 0; j < 256; ++j) {
        float4 k4 = sk[j];
        float dx = px - k4.x, dy = py - k4.y, dz = pz - k4.z;
        float d = dx * dx + dy * dy + dz * dz;
        if (d < bd2) {
            if (d < bd1) {
                bd2 = bd1; bi2 = bi1;
                if (d < bd0) { bd1 = bd0; bi1 = bi0; bd0 = d; bi0 = j; }
                else         { bd1 = d;   bi1 = j; }
            } else { bd2 = d; bi2 = j; }
        }
    }
    int gofs = ch * 256;
    size_t base = (((size_t)b * 4 + ch) * 3) * N_ + i;
    g_pd[base + 0 * N_] = bd0; g_pi[base + 0 * N_] = bi0 + gofs;
    g_pd[base + 1 * N_] = bd1; g_pi[base + 1 * N_] = bi1 + gofs;
    g_pd[base + 2 * N_] = bd2; g_pi[base + 2 * N_] = bi2 + gofs;
}

__global__ void __launch_bounds__(128) knn_merge_kernel() {
    int b = blockIdx.y;
    int i = blockIdx.x * 128 + threadIdx.x;
    float bd0 = 1e30f, bd1 = 1e30f, bd2 = 1e30f;
    int   bi0 = 0, bi1 = 0, bi2 = 0;
    #pragma unroll
    for (int ch = 0; ch < 4; ++ch) {
        #pragma unroll
        for (int t = 0; t < 3; ++t) {
            size_t base = (((size_t)b * 4 + ch) * 3 + t) * N_ + i;
            float d = g_pd[base];
            int   x = g_pi[base];
            if (d < bd2) {
                if (d < bd1) {
                    bd2 = bd1; bi2 = bi1;
                    if (d < bd0) { bd1 = bd0; bi1 = bi0; bd0 = d; bi0 = x; }
                    else         { bd1 = d;   bi1 = x; }
                } else { bd2 = d; bi2 = x; }
            }
        }
    }
    float r0 = 1.f / (bd0 + 1e-8f), r1 = 1.f / (bd1 + 1e-8f), r2 = 1.f / (bd2 + 1e-8f);
    float rs = r0 + r1 + r2;
    size_t base = (size_t)b * 3 * N_ + i;
    g_idx[base + 0 * N_] = bi0; g_idx[base + 1 * N_] = bi1; g_idx[base + 2 * N_] = bi2;
    g_w[base + 0 * N_] = r0 / rs; g_w[base + 1 * N_] = r1 / rs; g_w[base + 2 * N_] = r2 / rs;
}

// ---------------- three_interpolate ----------------------------------------------
__global__ void __launch_bounds__(256) interp_kernel(const float* __restrict__ kf) {
    int b = blockIdx.y;
    int cg = blockIdx.x;
    const int*   ib = g_idx + (size_t)b * 3 * N_;
    const float* wb = g_w   + (size_t)b * 3 * N_;
    for (int i = threadIdx.x; i < N_; i += blockDim.x) {
        int i0 = ib[i], i1 = ib[i + N_], i2 = ib[i + 2 * N_];
        float w0 = wb[i], w1 = wb[i + N_], w2 = wb[i + 2 * N_];
        #pragma unroll
        for (int cc = 0; cc < 8; ++cc) {
            int c = cg * 8 + cc;
            const float* row = kf + ((size_t)b * C2_ + c) * M_;
            g_interp[((size_t)b * C2_ + c) * N_ + i] = w0 * row[i0] + w1 * row[i1] + w2 * row[i2];
        }
    }
}

// ---------------- split-int8 IMMA GEMM -------------------------------------------
// X loader: thread t handles n = t&127, k-group ko=(t>>7)*8; quantize to hi/lo packed
template <int MODE>
__device__ __forceinline__ void loadQ(uint32_t w[4], int b, int nb, int chunk,
                                      int tid, const float* __restrict__ uf, float inv_s) {
    int n = tid & 127;
    int ko = (tid >> 7) * 8;
    int kbase = chunk * KC + ko;
    const float* col;
    if constexpr (MODE == 0) {
        col = (kbase < C2_) ? g_interp + ((size_t)b * C2_ + kbase) * N_
                            : uf + ((size_t)b * C1_ + (kbase - C2_)) * N_;
    } else {
        col = g_h1 + ((size_t)b * CO_ + kbase) * N_;
    }
    col += nb + n;
    uint32_t hi0 = 0, hi1 = 0, lo0 = 0, lo1 = 0;
    #pragma unroll
    for (int j = 0; j < 8; ++j) {
        float v = col[(size_t)j * N_];
        if constexpr (MODE == 1)
            v = fmaxf(fmaf(g_scale1[kbase + j], v, g_shift1[kbase + j]), 0.f);
        float x = v * inv_s;
        int ih = __float2int_rn(x);
        int il = __float2int_rn((x - (float)ih) * 128.f);
        uint32_t bh = (uint32_t)(ih & 0xFF);
        uint32_t bl = (uint32_t)(il & 0xFF);
        if (j < 4) { hi0 |= bh << (8 * j);       lo0 |= bl << (8 * j); }
        else       { hi1 |= bh << (8 * (j - 4)); lo1 |= bl << (8 * (j - 4)); }
    }
    w[0] = hi0; w[1] = hi1; w[2] = lo0; w[3] = lo1;
}
__device__ __forceinline__ void storeQ(char* dynB, const uint32_t w[4], int tid) {
    int n = tid & 127;
    int ko = (tid >> 7) * 8;
    uint32_t off = (uint32_t)(n * ROWBI + ko);
    *(uint2*)(dynB + off)       = make_uint2(w[0], w[1]);
    *(uint2*)(dynB + BHL + off) = make_uint2(w[2], w[3]);
}

// A fragments (weights): warp strip 32 co = 2 m16 frags, one ldmatrix.x4 each
__device__ __forceinline__ void ldA4(uint32_t a[2][4], uint32_t aBase, int wm, int lane) {
    int j = lane >> 3, rr = lane & 7;
    uint32_t koff = (uint32_t)((j >> 1) * 16);
    #pragma unroll
    for (int mf = 0; mf < 2; ++mf) {
        uint32_t row = (uint32_t)(wm * 32 + mf * 16 + (j & 1) * 8 + rr);
        ldmx4(a[mf], aBase + row * ROWBI + koff);
    }
}
// B fragments (X): warp strip 32 n = 4 n8 frags, two ldmatrix.x4
__device__ __forceinline__ void ldB4(uint32_t bb[8], uint32_t bBase, int wn, int lane) {
    int j = lane >> 3, rr = lane & 7;
    uint32_t koff = (uint32_t)((j & 1) * 16);
    #pragma unroll
    for (int q = 0; q < 2; ++q) {
        uint32_t row = (uint32_t)(wn * 32 + q * 16 + (j >> 1) * 8 + rr);
        ldmx4(&bb[q * 4], bBase + row * ROWBI + koff);
    }
}

template <int MODE>
__global__ void __launch_bounds__(512, 1) mma_gemm_kernel(const float* __restrict__ uf) {
    constexpr int Kdim = (MODE == 0) ? 512 : 256;
    constexpr int NC = Kdim / KC;

    extern __shared__ char dyn[];
    uint32_t sbase = smem_u32(dyn);

    int tid = threadIdx.x;
    int wid = tid >> 5, lane = tid & 31;
    int g = lane >> 2, tig = lane & 3;
    int wm = wid >> 2;          // 0..3 co strips of 32
    int wn = wid & 3;           // 0..3 n strips of 32
    int cot = blockIdx.x;
    int nb  = blockIdx.y * TN;
    int b   = blockIdx.z;

    const char* img = (const char*)((MODE == 0) ? g_w1q : g_w2q);

    float maxX = (MODE == 0) ? __uint_as_float(g_maxX1bits) : g_maxX2;
    float inv_s = 126.f / maxX;
    float s_x   = maxX * (1.f / 126.f);

    int accH[2][4][4], accX[2][4][4];
    #pragma unroll
    for (int mf = 0; mf < 2; ++mf)
        #pragma unroll
        for (int nf = 0; nf < 4; ++nf)
            #pragma unroll
            for (int v = 0; v < 4; ++v) { accH[mf][nf][v] = 0; accX[mf][nf][v] = 0; }

    auto cpA = [&](int chunk, uint32_t dst) {
        const char* cb = img + (size_t)chunk * (2 * 256 * ROWBI);
        #pragma unroll
        for (int j = 0; j < 3; ++j) {
            int u = tid + j * 512;
            if (u < 1280) {
                int hl = u / 640, rem = u - hl * 640;
                int row = rem / 5, u5 = rem - row * 5;
                CP_ASYNC16(dst + (uint32_t)(u * 16),
                           cb + (size_t)hl * (256 * ROWBI)
                              + (size_t)(cot * TM + row) * ROWBI + u5 * 16);
            }
        }
    };

    // prologue: chunk 0
    {
        cpA(0, sbase);
        CP_COMMIT();
        uint32_t w[4];
        loadQ<MODE>(w, b, nb, 0, tid, uf, inv_s);
        storeQ(dyn + BBASE, w, tid);
        CP_WAIT0();
        __syncthreads();
    }

    for (int c = 0; c < NC; ++c) {
        int p = c & 1, q = p ^ 1;
        uint32_t wq[4];
        if (c + 1 < NC) {
            cpA(c + 1, sbase + q * ASTG);
            CP_COMMIT();
            loadQ<MODE>(wq, b, nb, c + 1, tid, uf, inv_s);
        }

        uint32_t AhiB = sbase + p * ASTG;
        uint32_t AloB = AhiB + AHL;
        uint32_t BhiB = sbase + BBASE + p * BSTG;
        uint32_t BloB = BhiB + BHL;

        uint32_t a_h[2][4], a_l[2][4], bb[8];
        ldA4(a_h, AhiB, wm, lane);
        ldB4(bb, BhiB, wn, lane);
        #pragma unroll
        for (int mf = 0; mf < 2; ++mf)
            #pragma unroll
            for (int nf = 0; nf < 4; ++nf) imma16832(accH[mf][nf], a_h[mf], &bb[nf * 2]);
        ldA4(a_l, AloB, wm, lane);
        #pragma unroll
        for (int mf = 0; mf < 2; ++mf)
            #pragma unroll
            for (int nf = 0; nf < 4; ++nf) imma16832(accX[mf][nf], a_l[mf], &bb[nf * 2]);
        ldB4(bb, BloB, wn, lane);
        #pragma unroll
        for (int mf = 0; mf < 2; ++mf)
            #pragma unroll
            for (int nf = 0; nf < 4; ++nf) imma16832(accX[mf][nf], a_h[mf], &bb[nf * 2]);

        if (c + 1 < NC) {
            storeQ(dyn + BBASE + q * BSTG, wq, tid);
            CP_WAIT0();
        }
        __syncthreads();
    }

    // epilogue: dequant + store + fused BN stats (+h1 range for MODE 0)
    float* out  = (MODE == 0) ? g_h1  : g_h2;
    float* gsum = (MODE == 0) ? g_sum1 : g_sum2;
    float* gsq  = (MODE == 0) ? g_sq1  : g_sq2;
    const float* swr = (MODE == 0) ? g_swr1 : g_swr2;
    const float inv128 = 0.0078125f;
    #pragma unroll
    for (int mf = 0; mf < 2; ++mf) {
        int co0 = cot * TM + wm * 32 + mf * 16 + g;
        int co1 = co0 + 8;
        float f0 = s_x * swr[co0];
        float f1 = s_x * swr[co1];
        float s0 = 0.f, q0 = 0.f, s1 = 0.f, q1 = 0.f;
        float mx0 = -3.4e38f, mn0 = 3.4e38f, mx1 = -3.4e38f, mn1 = 3.4e38f;
        #pragma unroll
        for (int nf = 0; nf < 4; ++nf) {
            int n = nb + wn * 32 + nf * 8 + tig * 2;
            float va = f0 * ((float)accH[mf][nf][0] + (float)accX[mf][nf][0] * inv128);
            float vb = f0 * ((float)accH[mf][nf][1] + (float)accX[mf][nf][1] * inv128);
            float vc = f1 * ((float)accH[mf][nf][2] + (float)accX[mf][nf][2] * inv128);
            float vd = f1 * ((float)accH[mf][nf][3] + (float)accX[mf][nf][3] * inv128);
            *(float2*)(out + ((size_t)b * CO_ + co0) * N_ + n) = make_float2(va, vb);
            *(float2*)(out + ((size_t)b * CO_ + co1) * N_ + n) = make_float2(vc, vd);
            s0 += va + vb; q0 += va * va + vb * vb;
            s1 += vc + vd; q1 += vc * vc + vd * vd;
            if constexpr (MODE == 0) {
                mx0 = fmaxf(mx0, fmaxf(va, vb)); mn0 = fminf(mn0, fminf(va, vb));
                mx1 = fmaxf(mx1, fmaxf(vc, vd)); mn1 = fminf(mn1, fminf(vc, vd));
            }
        }
        #pragma unroll
        for (int o = 2; o > 0; o >>= 1) {
            s0 += __shfl_down_sync(0xffffffffu, s0, o);
            q0 += __shfl_down_sync(0xffffffffu, q0, o);
            s1 += __shfl_down_sync(0xffffffffu, s1, o);
            q1 += __shfl_down_sync(0xffffffffu, q1, o);
            if constexpr (MODE == 0) {
                mx0 = fmaxf(mx0, __shfl_down_sync(0xffffffffu, mx0, o));
                mn0 = fminf(mn0, __shfl_down_sync(0xffffffffu, mn0, o));
                mx1 = fmaxf(mx1, __shfl_down_sync(0xffffffffu, mx1, o));
                mn1 = fminf(mn1, __shfl_down_sync(0xffffffffu, mn1, o));
            }
        }
        if (tig == 0) {
            atomicAdd(&gsum[co0], s0); atomicAdd(&gsq[co0], q0);
            atomicAdd(&gsum[co1], s1); atomicAdd(&gsq[co1], q1);
            if constexpr (MODE == 0) {
                atomicMax(&g_h1maxE[co0], encf(mx0)); atomicMin(&g_h1minE[co0], encf(mn0));
                atomicMax(&g_h1maxE[co1], encf(mx1)); atomicMin(&g_h1minE[co1], encf(mn1));
            }
        }
    }
}

// ---------------- BN fold (+X2 scale for layer 1) --------------------------------
template <int MODE>
__global__ void __launch_bounds__(256) finalize_kernel(const float* __restrict__ g,
                                                       const float* __restrict__ bb) {
    int c = threadIdx.x;
    float inv = 1.f / (float)(B_ * N_);
    float s  = (MODE == 0) ? g_sum1[c] : g_sum2[c];
    float sq = (MODE == 0) ? g_sq1[c]  : g_sq2[c];
    float mean = s * inv;
    float var  = sq * inv - mean * mean;
    float rstd = rsqrtf(var + 1e-5f);
    float sc = g[c] * rstd;
    float sh = bb[c] - mean * sc;
    if constexpr (MODE == 0) {
        g_scale1[c] = sc; g_shift1[c] = sh;
        // exact bound on relu(bn1(h1)) from per-channel h1 range
        float hmx = decf(g_h1maxE[c]), hmn = decf(g_h1minE[c]);
        float cand = fmaxf(fmaxf(sc * hmx + sh, sc * hmn + sh), 0.f);
        #pragma unroll
        for (int o = 16; o > 0; o >>= 1)
            cand = fmaxf(cand, __shfl_xor_sync(0xffffffffu, cand, o));
        __shared__ float red[8];
        if ((c & 31) == 0) red[c >> 5] = cand;
        __syncthreads();
        if (c == 0) {
            float m = red[0];
            #pragma unroll
            for (int i = 1; i < 8; ++i) m = fmaxf(m, red[i]);
            g_maxX2 = fmaxf(m, 1e-30f);
        }
    } else {
        g_scale2[c] = sc; g_shift2[c] = sh;
    }
}

__global__ void __launch_bounds__(256) apply_kernel(float* __restrict__ out) {
    size_t idx = (size_t)blockIdx.x * blockDim.x + threadIdx.x;
    int c = (int)((idx * 4 / N_) % CO_);
    float4 v = ((const float4*)g_h2)[idx];
    float sc = g_scale2[c], sh = g_shift2[c];
    v.x = fmaxf(fmaf(sc, v.x, sh), 0.f);
    v.y = fmaxf(fmaf(sc, v.y, sh), 0.f);
    v.z = fmaxf(fmaf(sc, v.z, sh), 0.f);
    v.w = fmaxf(fmaf(sc, v.w, sh), 0.f);
    ((float4*)out)[idx] = v;
}

// ---------------- launch ----------------------------------------------------------
extern "C" void kernel_launch(void* const* d_in, const int* in_sizes, int n_in,
                              void* d_out, int out_size) {
    const float* unknown      = (const float*)d_in[0];
    const float* known        = (const float*)d_in[1];
    const float* unknow_feats = (const float*)d_in[2];
    const float* known_feats  = (const float*)d_in[3];
    const float* W1 = (const float*)d_in[4];
    const float* g1 = (const float*)d_in[5];
    const float* b1 = (const float*)d_in[6];
    const float* W2 = (const float*)d_in[7];
    const float* g2 = (const float*)d_in[8];
    const float* b2 = (const float*)d_in[9];
    float* out = (float*)d_out;

    static bool attr_done = false;
    if (!attr_done) {
        cudaFuncSetAttribute(mma_gemm_kernel<0>, cudaFuncAttributeMaxDynamicSharedMemorySize, SMEMI);
        cudaFuncSetAttribute(mma_gemm_kernel<1>, cudaFuncAttributeMaxDynamicSharedMemorySize, SMEMI);
        attr_done = true;
    }

    int8_t* w1q; cudaGetSymbolAddress((void**)&w1q, g_w1q);
    int8_t* w2q; cudaGetSymbolAddress((void**)&w2q, g_w2q);
    float* swr1; cudaGetSymbolAddress((void**)&swr1, g_swr1);
    float* swr2; cudaGetSymbolAddress((void**)&swr2, g_swr2);

    wquant_kernel<<<256, 128>>>(W1, 512, w1q, swr1, 1);
    wquant_kernel<<<256, 128>>>(W2, 256, w2q, swr2, 0);
    maxabs_kernel<<<2048, 256>>>(unknow_feats, B_ * C1_ * N_ / 4);
    maxabs_kernel<<<512, 256>>>(known_feats, B_ * C2_ * M_ / 4);
    knn_part_kernel<<<dim3(N_ / 128, 4, B_), 128>>>(unknown, known);
    knn_merge_kernel<<<dim3(N_ / 128, B_), 128>>>();
    interp_kernel<<<dim3(C2_ / 8, B_), 256>>>(known_feats);

    dim3 ggrid(CO_ / TM, N_ / TN, B_);
    mma_gemm_kernel<0><<<ggrid, 512, SMEMI>>>(unknow_feats);
    finalize_kernel<0><<<1, 256>>>(g1, b1);
    mma_gemm_kernel<1><<<ggrid, 512, SMEMI>>>(nullptr);
    finalize_kernel<1><<<1, 256>>>(g2, b2);
    apply_kernel<<<(size_t)B_ * CO_ * (N_ / 4) / 256, 256>>>(out);
}

// round 9
// speedup vs baseline: 2.7961x; 2.7961x over previous
#include <cuda_runtime.h>
#include <cuda_fp16.h>
#include <cstdint>
#include <cstddef>

#define B_   16
#define N_   4096
#define M_   1024
#define C1_  256
#define C2_  256
#define CO_  256

// GEMM tile geometry: 128co x 128n per block, 2 CTAs/SM
#define TM 128
#define TN 128
#define KC 32
#define ROWE 40               // fp16 elems per smem row (32 data + 8 pad) = 80B
#define ROWB 80
#define A_STAGE 10240         // 128 rows * 80B (weights: hi only)
#define B_BASE_ 20480
#define B_STAGE 20480         // hi + lo halves of X tile
#define B_HL    10240
#define SMEM_TOTAL 61440

// ---------------- scratch (device globals) ------------------------------------
__device__ float g_interp[(size_t)B_ * C2_ * N_];
__device__ float g_h1[(size_t)B_ * CO_ * N_];
__device__ float g_h2[(size_t)B_ * CO_ * N_];
__device__ int   g_idx[(size_t)B_ * 3 * N_];
__device__ float g_w[(size_t)B_ * 3 * N_];
__device__ float g_pd[(size_t)B_ * 4 * 3 * N_];
__device__ int   g_pi[(size_t)B_ * 4 * 3 * N_];
__device__ float g_sum1[CO_], g_sq1[CO_], g_scale1[CO_], g_shift1[CO_];
__device__ float g_sum2[CO_], g_sq2[CO_], g_scale2[CO_], g_shift2[CO_];
// fp16 weight smem-images: [chunk][256 co][ROWE]
__device__ __half g_w1img[16 * 256 * ROWE];
__device__ __half g_w2img[8 * 256 * ROWE];

// ---------------- helpers ------------------------------------------------------
__device__ __forceinline__ uint32_t smem_u32(const void* p) {
    uint32_t a;
    asm("{ .reg .u64 t; cvta.to.shared.u64 t, %1; cvt.u32.u64 %0, t; }" : "=r"(a) : "l"(p));
    return a;
}
#define CP_ASYNC16(dst, src) \
    asm volatile("cp.async.cg.shared.global [%0], [%1], 16;" :: "r"(dst), "l"(src))
#define CP_COMMIT() asm volatile("cp.async.commit_group;")
#define CP_WAIT0()  asm volatile("cp.async.wait_group 0;")

__device__ __forceinline__ void mma16816(float c[4], const uint32_t a[4], const uint32_t b[2]) {
    asm volatile(
        "mma.sync.aligned.m16n8k16.row.col.f32.f16.f16.f32 "
        "{%0,%1,%2,%3}, {%4,%5,%6,%7}, {%8,%9}, {%0,%1,%2,%3};"
        : "+f"(c[0]), "+f"(c[1]), "+f"(c[2]), "+f"(c[3])
        : "r"(a[0]), "r"(a[1]), "r"(a[2]), "r"(a[3]), "r"(b[0]), "r"(b[1]));
}
__device__ __forceinline__ void ldmx4(uint32_t r[4], uint32_t addr) {
    asm volatile("ldmatrix.sync.aligned.m8n8.x4.shared.b16 {%0,%1,%2,%3}, [%4];"
                 : "=r"(r[0]), "=r"(r[1]), "=r"(r[2]), "=r"(r[3]) : "r"(addr));
}

// ---------------- weight fp16 image (+stats zero folded in) ---------------------
__global__ void wsplit_img_kernel(const float* __restrict__ W, int Kdim, int total,
                                  __half* __restrict__ out, int do_zero) {
    int idx = blockIdx.x * 256 + threadIdx.x;
    if (do_zero && blockIdx.x == 0) {
        int t = threadIdx.x;
        g_sum1[t] = 0.f; g_sq1[t] = 0.f;
        g_sum2[t] = 0.f; g_sq2[t] = 0.f;
    }
    if (idx >= total) return;
    int kk = idx % ROWE;
    int co = (idx / ROWE) & 255;
    int chunk = idx / (ROWE * 256);
    float v = (kk < KC) ? W[(size_t)co * Kdim + chunk * KC + kk] : 0.f;
    out[idx] = __float2half_rn(v);
}

// ---------------- chunked three_nn ----------------------------------------------
__global__ void __launch_bounds__(128) knn_part_kernel(
    const float* __restrict__ unknown, const float* __restrict__ known) {
    __shared__ float4 sk[256];
    int b = blockIdx.z, ch = blockIdx.y;
    const float* kb = known + ((size_t)b * M_ + ch * 256) * 3;
    for (int j = threadIdx.x; j < 256; j += 128)
        sk[j] = make_float4(kb[j * 3 + 0], kb[j * 3 + 1], kb[j * 3 + 2], 0.f);
    __syncthreads();

    int i = blockIdx.x * 128 + threadIdx.x;
    const float* up = unknown + ((size_t)b * N_ + i) * 3;
    float px = up[0], py = up[1], pz = up[2];
    float bd0 = 1e30f, bd1 = 1e30f, bd2 = 1e30f;
    int   bi0 = 0, bi1 = 0, bi2 = 0;
    #pragma unroll 4
    for (int j = 0; j < 256; ++j) {
        float4 k4 = sk[j];
        float dx = px - k4.x, dy = py - k4.y, dz = pz - k4.z;
        float d = dx * dx + dy * dy + dz * dz;
        if (d < bd2) {
            if (d < bd1) {
                bd2 = bd1; bi2 = bi1;
                if (d < bd0) { bd1 = bd0; bi1 = bi0; bd0 = d; bi0 = j; }
                else         { bd1 = d;   bi1 = j; }
            } else { bd2 = d; bi2 = j; }
        }
    }
    int gofs = ch * 256;
    size_t base = (((size_t)b * 4 + ch) * 3) * N_ + i;
    g_pd[base + 0 * N_] = bd0; g_pi[base + 0 * N_] = bi0 + gofs;
    g_pd[base + 1 * N_] = bd1; g_pi[base + 1 * N_] = bi1 + gofs;
    g_pd[base + 2 * N_] = bd2; g_pi[base + 2 * N_] = bi2 + gofs;
}

__global__ void __launch_bounds__(128) knn_merge_kernel() {
    int b = blockIdx.y;
    int i = blockIdx.x * 128 + threadIdx.x;
    float bd0 = 1e30f, bd1 = 1e30f, bd2 = 1e30f;
    int   bi0 = 0, bi1 = 0, bi2 = 0;
    #pragma unroll
    for (int ch = 0; ch < 4; ++ch) {
        #pragma unroll
        for (int t = 0; t < 3; ++t) {
            size_t base = (((size_t)b * 4 + ch) * 3 + t) * N_ + i;
            float d = g_pd[base];
            int   x = g_pi[base];
            if (d < bd2) {
                if (d < bd1) {
                    bd2 = bd1; bi2 = bi1;
                    if (d < bd0) { bd1 = bd0; bi1 = bi0; bd0 = d; bi0 = x; }
                    else         { bd1 = d;   bi1 = x; }
                } else { bd2 = d; bi2 = x; }
            }
        }
    }
    float r0 = 1.f / (bd0 + 1e-8f), r1 = 1.f / (bd1 + 1e-8f), r2 = 1.f / (bd2 + 1e-8f);
    float rs = r0 + r1 + r2;
    size_t base = (size_t)b * 3 * N_ + i;
    g_idx[base + 0 * N_] = bi0; g_idx[base + 1 * N_] = bi1; g_idx[base + 2 * N_] = bi2;
    g_w[base + 0 * N_] = r0 / rs; g_w[base + 1 * N_] = r1 / rs; g_w[base + 2 * N_] = r2 / rs;
}

// ---------------- three_interpolate ----------------------------------------------
__global__ void __launch_bounds__(256) interp_kernel(const float* __restrict__ kf) {
    int b = blockIdx.y;
    int cg = blockIdx.x;
    const int*   ib = g_idx + (size_t)b * 3 * N_;
    const float* wb = g_w   + (size_t)b * 3 * N_;
    for (int i = threadIdx.x; i < N_; i += blockDim.x) {
        int i0 = ib[i], i1 = ib[i + N_], i2 = ib[i + 2 * N_];
        float w0 = wb[i], w1 = wb[i + N_], w2 = wb[i + 2 * N_];
        #pragma unroll
        for (int cc = 0; cc < 8; ++cc) {
            int c = cg * 8 + cc;
            const float* row = kf + ((size_t)b * C2_ + c) * M_;
            g_interp[((size_t)b * C2_ + c) * N_ + i] = w0 * row[i0] + w1 * row[i1] + w2 * row[i2];
        }
    }
}

// ---------------- split-fp16 HMMA GEMM (2-pass, 128x128 tiles, 2 CTAs/SM) --------
template <int MODE>
__device__ __forceinline__ void loadB_regs(float4 xr[4], int b, int nb, int chunk,
                                           int tid, const float* __restrict__ uf) {
    int kp = tid >> 4;
    int n8 = (tid & 15) * 8;
    int k = chunk * KC + kp * 2;
    const float* r0;
    if constexpr (MODE == 0) {
        r0 = (k < C2_) ? g_interp + ((size_t)b * C2_ + k) * N_
                       : uf       + ((size_t)b * C1_ + (k - C2_)) * N_;
    } else {
        r0 = g_h1 + ((size_t)b * CO_ + k) * N_;
    }
    const float* p0 = r0 + nb + n8;
    xr[0] = *(const float4*)(p0);
    xr[1] = *(const float4*)(p0 + 4);
    xr[2] = *(const float4*)(p0 + N_);
    xr[3] = *(const float4*)(p0 + N_ + 4);
}

template <int MODE>
__device__ __forceinline__ void storeB(uint32_t* __restrict__ bhi, uint32_t* __restrict__ blo,
                                       float4 xr[4], int chunk, int tid) {
    int kp = tid >> 4;
    int n8 = (tid & 15) * 8;
    float x0[8] = {xr[0].x, xr[0].y, xr[0].z, xr[0].w, xr[1].x, xr[1].y, xr[1].z, xr[1].w};
    float x1[8] = {xr[2].x, xr[2].y, xr[2].z, xr[2].w, xr[3].x, xr[3].y, xr[3].z, xr[3].w};
    if constexpr (MODE == 1) {
        int kg = chunk * KC + kp * 2;
        float s0 = g_scale1[kg],     sh0 = g_shift1[kg];
        float s1 = g_scale1[kg + 1], sh1 = g_shift1[kg + 1];
        #pragma unroll
        for (int i = 0; i < 8; ++i) {
            x0[i] = fmaxf(fmaf(s0, x0[i], sh0), 0.f);
            x1[i] = fmaxf(fmaf(s1, x1[i], sh1), 0.f);
        }
    }
    #pragma unroll
    for (int i = 0; i < 8; ++i) {
        int n = n8 + i;
        __half h0 = __float2half_rn(x0[i]);
        __half l0 = __float2half_rn(x0[i] - __half2float(h0));
        __half h1 = __float2half_rn(x1[i]);
        __half l1 = __float2half_rn(x1[i] - __half2float(h1));
        uint32_t hw = (uint32_t)__half_as_ushort(h0) | ((uint32_t)__half_as_ushort(h1) << 16);
        uint32_t lw = (uint32_t)__half_as_ushort(l0) | ((uint32_t)__half_as_ushort(l1) << 16);
        int m3 = (n >> 3) & 3;
        int w = n * 20 + (((kp >> 2) ^ m3) << 2) + (kp & 3);
        bhi[w] = hw;
        blo[w] = lw;
    }
}

// A fragments via ldmatrix.x4: rows = co (32-row warp strip), 80B rows
__device__ __forceinline__ void ldA4(uint32_t a[2][4], uint32_t aBase,
                                     int wm, int lane, int ks) {
    int j = lane >> 3, rr = lane & 7;
    uint32_t koff = (uint32_t)(ks * 32 + (j >> 1) * 16);
    uint32_t rbase = (uint32_t)((wm * 32 + (j & 1) * 8 + rr) * ROWB);
    #pragma unroll
    for (int t = 0; t < 2; ++t)
        ldmx4(a[t], aBase + rbase + (uint32_t)(t * 16 * ROWB) + koff);
}
// B fragments via ldmatrix.x4: rows = n (64-row warp strip), chunk-swizzled
__device__ __forceinline__ void ldB4(uint32_t bb[16], uint32_t bBase,
                                     int wn, int lane, int ks) {
    int j = lane >> 3, rr = lane & 7;
    #pragma unroll
    for (int up = 0; up < 4; ++up) {
        int u = up * 2;
        int grp = u + (j >> 1);
        int chunk = ks * 2 + (j & 1);
        int m3 = grp & 3;
        uint32_t addr = bBase + (uint32_t)(((wn * 8 + grp) * 8 + rr) * ROWB)
                      + (uint32_t)((chunk ^ m3) * 16);
        ldmx4(&bb[u * 2], addr);
    }
}

template <int MODE>
__global__ void __launch_bounds__(256, 2) mma_gemm_kernel(const float* __restrict__ uf) {
    constexpr int Kdim = (MODE == 0) ? 512 : 256;
    constexpr int NC = Kdim / KC;

    extern __shared__ char dyn[];
    uint32_t sbase = smem_u32(dyn);

    int tid = threadIdx.x;
    int wid = tid >> 5, lane = tid & 31;
    int g = lane >> 2, tig = lane & 3;
    int wm = wid >> 1;          // 0..3, co strips of 32
    int wn = wid & 1;           // 0..1, n strips of 64
    int cot = blockIdx.x;       // co-tile 0/1 (fastest -> L2 X reuse)
    int nb  = blockIdx.y * TN;
    int b   = blockIdx.z;

    const __half* img = (MODE == 0) ? g_w1img : g_w2img;
    const char* imgbase = (const char*)img + (size_t)cot * TM * ROWB;

    float acc[2][8][4];
    #pragma unroll
    for (int t = 0; t < 2; ++t)
        #pragma unroll
        for (int u = 0; u < 8; ++u)
            #pragma unroll
            for (int v = 0; v < 4; ++v) acc[t][u][v] = 0.f;

    // cp.async of one A stage (10KB): 640 x 16B with 256 threads
    auto cpA = [&](int chunk, uint32_t dst) {
        const char* cbase = imgbase + (size_t)chunk * (256 * ROWB);
        #pragma unroll
        for (int j = 0; j < 3; ++j) {
            int v = tid + j * 256;
            if (v < 640)
                CP_ASYNC16(dst + (uint32_t)(v * 16), cbase + v * 16);
        }
    };

    // prologue: chunk 0
    {
        cpA(0, sbase);
        CP_COMMIT();
        float4 xr[4];
        loadB_regs<MODE>(xr, b, nb, 0, tid, uf);
        storeB<MODE>((uint32_t*)(dyn + B_BASE_), (uint32_t*)(dyn + B_BASE_ + B_HL), xr, 0, tid);
        CP_WAIT0();
        __syncthreads();
    }

    for (int c = 0; c < NC; ++c) {
        int p = c & 1, q = p ^ 1;
        float4 xr[4];
        if (c + 1 < NC) {
            cpA(c + 1, sbase + q * A_STAGE);
            CP_COMMIT();
            loadB_regs<MODE>(xr, b, nb, c + 1, tid, uf);
        }

        uint32_t AB   = sbase + p * A_STAGE;
        uint32_t BhiB = sbase + B_BASE_ + p * B_STAGE;
        uint32_t BloB = BhiB + B_HL;

        uint32_t a[2][4], bb[16];
        #pragma unroll
        for (int ks = 0; ks < 2; ++ks) {
            ldA4(a, AB, wm, lane, ks);
            ldB4(bb, BhiB, wn, lane, ks);
            #pragma unroll
            for (int t = 0; t < 2; ++t)
                #pragma unroll
                for (int u = 0; u < 8; ++u) mma16816(acc[t][u], a[t], &bb[u * 2]);
            ldB4(bb, BloB, wn, lane, ks);
            #pragma unroll
            for (int t = 0; t < 2; ++t)
                #pragma unroll
                for (int u = 0; u < 8; ++u) mma16816(acc[t][u], a[t], &bb[u * 2]);
        }

        if (c + 1 < NC) {
            storeB<MODE>((uint32_t*)(dyn + B_BASE_ + q * B_STAGE),
                         (uint32_t*)(dyn + B_BASE_ + q * B_STAGE + B_HL), xr, c + 1, tid);
            CP_WAIT0();
        }
        __syncthreads();
    }

    // epilogue: store + fused BN stats
    float* out  = (MODE == 0) ? g_h1  : g_h2;
    float* gsum = (MODE == 0) ? g_sum1 : g_sum2;
    float* gsq  = (MODE == 0) ? g_sq1  : g_sq2;
    #pragma unroll
    for (int t = 0; t < 2; ++t) {
        int co0 = cot * TM + wm * 32 + t * 16 + g;
        int co1 = co0 + 8;
        float s0 = 0.f, q0 = 0.f, s1 = 0.f, q1 = 0.f;
        #pragma unroll
        for (int u = 0; u < 8; ++u) {
            int n = nb + wn * 64 + u * 8 + tig * 2;
            float2 v0 = make_float2(acc[t][u][0], acc[t][u][1]);
            float2 v1 = make_float2(acc[t][u][2], acc[t][u][3]);
            *(float2*)(out + ((size_t)b * CO_ + co0) * N_ + n) = v0;
            *(float2*)(out + ((size_t)b * CO_ + co1) * N_ + n) = v1;
            s0 += v0.x + v0.y; q0 += v0.x * v0.x + v0.y * v0.y;
            s1 += v1.x + v1.y; q1 += v1.x * v1.x + v1.y * v1.y;
        }
        #pragma unroll
        for (int o = 2; o > 0; o >>= 1) {
            s0 += __shfl_down_sync(0xffffffffu, s0, o);
            q0 += __shfl_down_sync(0xffffffffu, q0, o);
            s1 += __shfl_down_sync(0xffffffffu, s1, o);
            q1 += __shfl_down_sync(0xffffffffu, q1, o);
        }
        if (tig == 0) {
            atomicAdd(&gsum[co0], s0); atomicAdd(&gsq[co0], q0);
            atomicAdd(&gsum[co1], s1); atomicAdd(&gsq[co1], q1);
        }
    }
}

// ---------------- BN fold + final apply -----------------------------------------
template <int MODE>
__global__ void finalize_kernel(const float* __restrict__ g, const float* __restrict__ bb) {
    int c = threadIdx.x;
    float inv = 1.f / (float)(B_ * N_);
    float s  = (MODE == 0) ? g_sum1[c] : g_sum2[c];
    float sq = (MODE == 0) ? g_sq1[c]  : g_sq2[c];
    float mean = s * inv;
    float var  = sq * inv - mean * mean;
    float rstd = rsqrtf(var + 1e-5f);
    float sc = g[c] * rstd;
    float sh = bb[c] - mean * sc;
    if (MODE == 0) { g_scale1[c] = sc; g_shift1[c] = sh; }
    else           { g_scale2[c] = sc; g_shift2[c] = sh; }
}

__global__ void __launch_bounds__(256) apply_kernel(float* __restrict__ out) {
    size_t idx = (size_t)blockIdx.x * blockDim.x + threadIdx.x;
    int c = (int)((idx * 4 / N_) % CO_);
    float4 v = ((const float4*)g_h2)[idx];
    float sc = g_scale2[c], sh = g_shift2[c];
    v.x = fmaxf(fmaf(sc, v.x, sh), 0.f);
    v.y = fmaxf(fmaf(sc, v.y, sh), 0.f);
    v.z = fmaxf(fmaf(sc, v.z, sh), 0.f);
    v.w = fmaxf(fmaf(sc, v.w, sh), 0.f);
    ((float4*)out)[idx] = v;
}

// ---------------- launch ----------------------------------------------------------
extern "C" void kernel_launch(void* const* d_in, const int* in_sizes, int n_in,
                              void* d_out, int out_size) {
    const float* unknown      = (const float*)d_in[0];
    const float* known        = (const float*)d_in[1];
    const float* unknow_feats = (const float*)d_in[2];
    const float* known_feats  = (const float*)d_in[3];
    const float* W1 = (const float*)d_in[4];
    const float* g1 = (const float*)d_in[5];
    const float* b1 = (const float*)d_in[6];
    const float* W2 = (const float*)d_in[7];
    const float* g2 = (const float*)d_in[8];
    const float* b2 = (const float*)d_in[9];
    float* out = (float*)d_out;

    static bool attr_done = false;
    if (!attr_done) {
        cudaFuncSetAttribute(mma_gemm_kernel<0>, cudaFuncAttributeMaxDynamicSharedMemorySize, SMEM_TOTAL);
        cudaFuncSetAttribute(mma_gemm_kernel<1>, cudaFuncAttributeMaxDynamicSharedMemorySize, SMEM_TOTAL);
        attr_done = true;
    }

    __half* w1img; cudaGetSymbolAddress((void**)&w1img, g_w1img);
    __half* w2img; cudaGetSymbolAddress((void**)&w2img, g_w2img);
    {
        int tot1 = 16 * 256 * ROWE;
        wsplit_img_kernel<<<(tot1 + 255) / 256, 256>>>(W1, 512, tot1, w1img, 1);
        int tot2 = 8 * 256 * ROWE;
        wsplit_img_kernel<<<(tot2 + 255) / 256, 256>>>(W2, 256, tot2, w2img, 0);
    }
    knn_part_kernel<<<dim3(N_ / 128, 4, B_), 128>>>(unknown, known);
    knn_merge_kernel<<<dim3(N_ / 128, B_), 128>>>();
    interp_kernel<<<dim3(C2_ / 8, B_), 256>>>(known_feats);

    dim3 ggrid(CO_ / TM, N_ / TN, B_);
    mma_gemm_kernel<0><<<ggrid, 256, SMEM_TOTAL>>>(unknow_feats);
    finalize_kernel<0><<<1, 256>>>(g1, b1);
    mma_gemm_kernel<1><<<ggrid, 256, SMEM_TOTAL>>>(nullptr);
    finalize_kernel<1><<<1, 256>>>(g2, b2);
    apply_kernel<<<(size_t)B_ * CO_ * (N_ / 4) / 256, 256>>>(out);
}

// round 10
// speedup vs baseline: 3.2370x; 1.1577x over previous
#include <cuda_runtime.h>
#include <cuda_fp16.h>
#include <cstdint>
#include <cstddef>

#define B_   16
#define N_   4096
#define M_   1024
#define C1_  256
#define C2_  256
#define CO_  256

// GEMM tile geometry: 128co x 128n per block, 2 CTAs/SM, single-pass fp16
#define TM 128
#define TN 128
#define KC 32
#define ROWE 40               // fp16 elems per smem row (32 data + 8 pad) = 80B
#define ROWB 80
#define A_STAGE 10240         // 128 rows * 80B
#define B_BASE_ 20480
#define B_STAGE 10240
#define SMEM_TOTAL 40960

// ---------------- scratch (device globals) ------------------------------------
__device__ float g_interp[(size_t)B_ * C2_ * N_];
__device__ float g_h1[(size_t)B_ * CO_ * N_];
__device__ float g_h2[(size_t)B_ * CO_ * N_];
__device__ int   g_idx[(size_t)B_ * 3 * N_];
__device__ float g_w[(size_t)B_ * 3 * N_];
__device__ float g_pd[(size_t)B_ * 4 * 3 * N_];
__device__ int   g_pi[(size_t)B_ * 4 * 3 * N_];
__device__ float g_sum1[CO_], g_sq1[CO_], g_scale1[CO_], g_shift1[CO_];
__device__ float g_sum2[CO_], g_sq2[CO_], g_scale2[CO_], g_shift2[CO_];
// fp16 weight smem-images: [chunk][256 co][ROWE]
__device__ __half g_w1img[16 * 256 * ROWE];
__device__ __half g_w2img[8 * 256 * ROWE];

// ---------------- helpers ------------------------------------------------------
__device__ __forceinline__ uint32_t smem_u32(const void* p) {
    uint32_t a;
    asm("{ .reg .u64 t; cvta.to.shared.u64 t, %1; cvt.u32.u64 %0, t; }" : "=r"(a) : "l"(p));
    return a;
}
#define CP_ASYNC16(dst, src) \
    asm volatile("cp.async.cg.shared.global [%0], [%1], 16;" :: "r"(dst), "l"(src))
#define CP_COMMIT() asm volatile("cp.async.commit_group;")
#define CP_WAIT0()  asm volatile("cp.async.wait_group 0;")

__device__ __forceinline__ void mma16816(float c[4], const uint32_t a[4], const uint32_t b[2]) {
    asm volatile(
        "mma.sync.aligned.m16n8k16.row.col.f32.f16.f16.f32 "
        "{%0,%1,%2,%3}, {%4,%5,%6,%7}, {%8,%9}, {%0,%1,%2,%3};"
        : "+f"(c[0]), "+f"(c[1]), "+f"(c[2]), "+f"(c[3])
        : "r"(a[0]), "r"(a[1]), "r"(a[2]), "r"(a[3]), "r"(b[0]), "r"(b[1]));
}
__device__ __forceinline__ void ldmx4(uint32_t r[4], uint32_t addr) {
    asm volatile("ldmatrix.sync.aligned.m8n8.x4.shared.b16 {%0,%1,%2,%3}, [%4];"
                 : "=r"(r[0]), "=r"(r[1]), "=r"(r[2]), "=r"(r[3]) : "r"(addr));
}

// ---------------- weight fp16 image (+stats zero folded in) ---------------------
__global__ void wsplit_img_kernel(const float* __restrict__ W, int Kdim, int total,
                                  __half* __restrict__ out, int do_zero) {
    int idx = blockIdx.x * 256 + threadIdx.x;
    if (do_zero && blockIdx.x == 0) {
        int t = threadIdx.x;
        g_sum1[t] = 0.f; g_sq1[t] = 0.f;
        g_sum2[t] = 0.f; g_sq2[t] = 0.f;
    }
    if (idx >= total) return;
    int kk = idx % ROWE;
    int co = (idx / ROWE) & 255;
    int chunk = idx / (ROWE * 256);
    float v = (kk < KC) ? W[(size_t)co * Kdim + chunk * KC + kk] : 0.f;
    out[idx] = __float2half_rn(v);
}

// ---------------- chunked three_nn ----------------------------------------------
__global__ void __launch_bounds__(128) knn_part_kernel(
    const float* __restrict__ unknown, const float* __restrict__ known) {
    __shared__ float4 sk[256];
    int b = blockIdx.z, ch = blockIdx.y;
    const float* kb = known + ((size_t)b * M_ + ch * 256) * 3;
    for (int j = threadIdx.x; j < 256; j += 128)
        sk[j] = make_float4(kb[j * 3 + 0], kb[j * 3 + 1], kb[j * 3 + 2], 0.f);
    __syncthreads();

    int i = blockIdx.x * 128 + threadIdx.x;
    const float* up = unknown + ((size_t)b * N_ + i) * 3;
    float px = up[0], py = up[1], pz = up[2];
    float bd0 = 1e30f, bd1 = 1e30f, bd2 = 1e30f;
    int   bi0 = 0, bi1 = 0, bi2 = 0;
    #pragma unroll 4
    for (int j = 0; j < 256; ++j) {
        float4 k4 = sk[j];
        float dx = px - k4.x, dy = py - k4.y, dz = pz - k4.z;
        float d = dx * dx + dy * dy + dz * dz;
        if (d < bd2) {
            if (d < bd1) {
                bd2 = bd1; bi2 = bi1;
                if (d < bd0) { bd1 = bd0; bi1 = bi0; bd0 = d; bi0 = j; }
                else         { bd1 = d;   bi1 = j; }
            } else { bd2 = d; bi2 = j; }
        }
    }
    int gofs = ch * 256;
    size_t base = (((size_t)b * 4 + ch) * 3) * N_ + i;
    g_pd[base + 0 * N_] = bd0; g_pi[base + 0 * N_] = bi0 + gofs;
    g_pd[base + 1 * N_] = bd1; g_pi[base + 1 * N_] = bi1 + gofs;
    g_pd[base + 2 * N_] = bd2; g_pi[base + 2 * N_] = bi2 + gofs;
}

__global__ void __launch_bounds__(128) knn_merge_kernel() {
    int b = blockIdx.y;
    int i = blockIdx.x * 128 + threadIdx.x;
    float bd0 = 1e30f, bd1 = 1e30f, bd2 = 1e30f;
    int   bi0 = 0, bi1 = 0, bi2 = 0;
    #pragma unroll
    for (int ch = 0; ch < 4; ++ch) {
        #pragma unroll
        for (int t = 0; t < 3; ++t) {
            size_t base = (((size_t)b * 4 + ch) * 3 + t) * N_ + i;
            float d = g_pd[base];
            int   x = g_pi[base];
            if (d < bd2) {
                if (d < bd1) {
                    bd2 = bd1; bi2 = bi1;
                    if (d < bd0) { bd1 = bd0; bi1 = bi0; bd0 = d; bi0 = x; }
                    else         { bd1 = d;   bi1 = x; }
                } else { bd2 = d; bi2 = x; }
            }
        }
    }
    float r0 = 1.f / (bd0 + 1e-8f), r1 = 1.f / (bd1 + 1e-8f), r2 = 1.f / (bd2 + 1e-8f);
    float rs = r0 + r1 + r2;
    size_t base = (size_t)b * 3 * N_ + i;
    g_idx[base + 0 * N_] = bi0; g_idx[base + 1 * N_] = bi1; g_idx[base + 2 * N_] = bi2;
    g_w[base + 0 * N_] = r0 / rs; g_w[base + 1 * N_] = r1 / rs; g_w[base + 2 * N_] = r2 / rs;
}

// ---------------- three_interpolate ----------------------------------------------
__global__ void __launch_bounds__(256) interp_kernel(const float* __restrict__ kf) {
    int b = blockIdx.y;
    int cg = blockIdx.x;
    const int*   ib = g_idx + (size_t)b * 3 * N_;
    const float* wb = g_w   + (size_t)b * 3 * N_;
    for (int i = threadIdx.x; i < N_; i += blockDim.x) {
        int i0 = ib[i], i1 = ib[i + N_], i2 = ib[i + 2 * N_];
        float w0 = wb[i], w1 = wb[i + N_], w2 = wb[i + 2 * N_];
        #pragma unroll
        for (int cc = 0; cc < 8; ++cc) {
            int c = cg * 8 + cc;
            const float* row = kf + ((size_t)b * C2_ + c) * M_;
            g_interp[((size_t)b * C2_ + c) * N_ + i] = w0 * row[i0] + w1 * row[i1] + w2 * row[i2];
        }
    }
}

// ---------------- single-pass fp16 HMMA GEMM (128x128 tiles, 2 CTAs/SM) ----------
template <int MODE>
__device__ __forceinline__ void loadB_regs(float4 xr[4], int b, int nb, int chunk,
                                           int tid, const float* __restrict__ uf) {
    int kp = tid >> 4;
    int n8 = (tid & 15) * 8;
    int k = chunk * KC + kp * 2;
    const float* r0;
    if constexpr (MODE == 0) {
        r0 = (k < C2_) ? g_interp + ((size_t)b * C2_ + k) * N_
                       : uf       + ((size_t)b * C1_ + (k - C2_)) * N_;
    } else {
        r0 = g_h1 + ((size_t)b * CO_ + k) * N_;
    }
    const float* p0 = r0 + nb + n8;
    xr[0] = *(const float4*)(p0);
    xr[1] = *(const float4*)(p0 + 4);
    xr[2] = *(const float4*)(p0 + N_);
    xr[3] = *(const float4*)(p0 + N_ + 4);
}

template <int MODE>
__device__ __forceinline__ void storeB(uint32_t* __restrict__ bs,
                                       float4 xr[4], int chunk, int tid) {
    int kp = tid >> 4;
    int n8 = (tid & 15) * 8;
    float x0[8] = {xr[0].x, xr[0].y, xr[0].z, xr[0].w, xr[1].x, xr[1].y, xr[1].z, xr[1].w};
    float x1[8] = {xr[2].x, xr[2].y, xr[2].z, xr[2].w, xr[3].x, xr[3].y, xr[3].z, xr[3].w};
    if constexpr (MODE == 1) {
        int kg = chunk * KC + kp * 2;
        float s0 = g_scale1[kg],     sh0 = g_shift1[kg];
        float s1 = g_scale1[kg + 1], sh1 = g_shift1[kg + 1];
        #pragma unroll
        for (int i = 0; i < 8; ++i) {
            x0[i] = fmaxf(fmaf(s0, x0[i], sh0), 0.f);
            x1[i] = fmaxf(fmaf(s1, x1[i], sh1), 0.f);
        }
    }
    #pragma unroll
    for (int i = 0; i < 8; ++i) {
        int n = n8 + i;
        __half h0 = __float2half_rn(x0[i]);
        __half h1 = __float2half_rn(x1[i]);
        uint32_t hw = (uint32_t)__half_as_ushort(h0) | ((uint32_t)__half_as_ushort(h1) << 16);
        int m3 = (n >> 3) & 3;
        int w = n * 20 + (((kp >> 2) ^ m3) << 2) + (kp & 3);
        bs[w] = hw;
    }
}

// A fragments via ldmatrix.x4: rows = co (32-row warp strip), 80B rows
__device__ __forceinline__ void ldA4(uint32_t a[2][4], uint32_t aBase,
                                     int wm, int lane, int ks) {
    int j = lane >> 3, rr = lane & 7;
    uint32_t koff = (uint32_t)(ks * 32 + (j >> 1) * 16);
    uint32_t rbase = (uint32_t)((wm * 32 + (j & 1) * 8 + rr) * ROWB);
    #pragma unroll
    for (int t = 0; t < 2; ++t)
        ldmx4(a[t], aBase + rbase + (uint32_t)(t * 16 * ROWB) + koff);
}
// B fragments via ldmatrix.x4: rows = n (64-row warp strip), chunk-swizzled
__device__ __forceinline__ void ldB4(uint32_t bb[16], uint32_t bBase,
                                     int wn, int lane, int ks) {
    int j = lane >> 3, rr = lane & 7;
    #pragma unroll
    for (int up = 0; up < 4; ++up) {
        int u = up * 2;
        int grp = u + (j >> 1);
        int chunk = ks * 2 + (j & 1);
        int m3 = grp & 3;
        uint32_t addr = bBase + (uint32_t)(((wn * 8 + grp) * 8 + rr) * ROWB)
                      + (uint32_t)((chunk ^ m3) * 16);
        ldmx4(&bb[u * 2], addr);
    }
}

template <int MODE>
__global__ void __launch_bounds__(256, 2) mma_gemm_kernel(const float* __restrict__ uf) {
    constexpr int Kdim = (MODE == 0) ? 512 : 256;
    constexpr int NC = Kdim / KC;

    extern __shared__ char dyn[];
    uint32_t sbase = smem_u32(dyn);

    int tid = threadIdx.x;
    int wid = tid >> 5, lane = tid & 31;
    int g = lane >> 2, tig = lane & 3;
    int wm = wid >> 1;          // 0..3, co strips of 32
    int wn = wid & 1;           // 0..1, n strips of 64
    int cot = blockIdx.x;       // co-tile 0/1 (fastest -> L2 X reuse)
    int nb  = blockIdx.y * TN;
    int b   = blockIdx.z;

    const __half* img = (MODE == 0) ? g_w1img : g_w2img;
    const char* imgbase = (const char*)img + (size_t)cot * TM * ROWB;

    float acc[2][8][4];
    #pragma unroll
    for (int t = 0; t < 2; ++t)
        #pragma unroll
        for (int u = 0; u < 8; ++u)
            #pragma unroll
            for (int v = 0; v < 4; ++v) acc[t][u][v] = 0.f;

    // cp.async of one A stage (10KB): 640 x 16B with 256 threads
    auto cpA = [&](int chunk, uint32_t dst) {
        const char* cbase = imgbase + (size_t)chunk * (256 * ROWB);
        #pragma unroll
        for (int j = 0; j < 3; ++j) {
            int v = tid + j * 256;
            if (v < 640)
                CP_ASYNC16(dst + (uint32_t)(v * 16), cbase + v * 16);
        }
    };

    // prologue: chunk 0
    {
        cpA(0, sbase);
        CP_COMMIT();
        float4 xr[4];
        loadB_regs<MODE>(xr, b, nb, 0, tid, uf);
        storeB<MODE>((uint32_t*)(dyn + B_BASE_), xr, 0, tid);
        CP_WAIT0();
        __syncthreads();
    }

    for (int c = 0; c < NC; ++c) {
        int p = c & 1, q = p ^ 1;
        float4 xr[4];
        if (c + 1 < NC) {
            cpA(c + 1, sbase + q * A_STAGE);
            CP_COMMIT();
            loadB_regs<MODE>(xr, b, nb, c + 1, tid, uf);
        }

        uint32_t AB = sbase + p * A_STAGE;
        uint32_t BB = sbase + B_BASE_ + p * B_STAGE;

        uint32_t a[2][4], bb[16];
        #pragma unroll
        for (int ks = 0; ks < 2; ++ks) {
            ldA4(a, AB, wm, lane, ks);
            ldB4(bb, BB, wn, lane, ks);
            #pragma unroll
            for (int t = 0; t < 2; ++t)
                #pragma unroll
                for (int u = 0; u < 8; ++u) mma16816(acc[t][u], a[t], &bb[u * 2]);
        }

        if (c + 1 < NC) {
            storeB<MODE>((uint32_t*)(dyn + B_BASE_ + q * B_STAGE), xr, c + 1, tid);
            CP_WAIT0();
        }
        __syncthreads();
    }

    // epilogue: store + fused BN stats
    float* out  = (MODE == 0) ? g_h1  : g_h2;
    float* gsum = (MODE == 0) ? g_sum1 : g_sum2;
    float* gsq  = (MODE == 0) ? g_sq1  : g_sq2;
    #pragma unroll
    for (int t = 0; t < 2; ++t) {
        int co0 = cot * TM + wm * 32 + t * 16 + g;
        int co1 = co0 + 8;
        float s0 = 0.f, q0 = 0.f, s1 = 0.f, q1 = 0.f;
        #pragma unroll
        for (int u = 0; u < 8; ++u) {
            int n = nb + wn * 64 + u * 8 + tig * 2;
            float2 v0 = make_float2(acc[t][u][0], acc[t][u][1]);
            float2 v1 = make_float2(acc[t][u][2], acc[t][u][3]);
            *(float2*)(out + ((size_t)b * CO_ + co0) * N_ + n) = v0;
            *(float2*)(out + ((size_t)b * CO_ + co1) * N_ + n) = v1;
            s0 += v0.x + v0.y; q0 += v0.x * v0.x + v0.y * v0.y;
            s1 += v1.x + v1.y; q1 += v1.x * v1.x + v1.y * v1.y;
        }
        #pragma unroll
        for (int o = 2; o > 0; o >>= 1) {
            s0 += __shfl_down_sync(0xffffffffu, s0, o);
            q0 += __shfl_down_sync(0xffffffffu, q0, o);
            s1 += __shfl_down_sync(0xffffffffu, s1, o);
            q1 += __shfl_down_sync(0xffffffffu, q1, o);
        }
        if (tig == 0) {
            atomicAdd(&gsum[co0], s0); atomicAdd(&gsq[co0], q0);
            atomicAdd(&gsum[co1], s1); atomicAdd(&gsq[co1], q1);
        }
    }
}

// ---------------- BN fold + final apply -----------------------------------------
template <int MODE>
__global__ void finalize_kernel(const float* __restrict__ g, const float* __restrict__ bb) {
    int c = threadIdx.x;
    float inv = 1.f / (float)(B_ * N_);
    float s  = (MODE == 0) ? g_sum1[c] : g_sum2[c];
    float sq = (MODE == 0) ? g_sq1[c]  : g_sq2[c];
    float mean = s * inv;
    float var  = sq * inv - mean * mean;
    float rstd = rsqrtf(var + 1e-5f);
    float sc = g[c] * rstd;
    float sh = bb[c] - mean * sc;
    if (MODE == 0) { g_scale1[c] = sc; g_shift1[c] = sh; }
    else           { g_scale2[c] = sc; g_shift2[c] = sh; }
}

__global__ void __launch_bounds__(256) apply_kernel(float* __restrict__ out) {
    size_t idx = (size_t)blockIdx.x * blockDim.x + threadIdx.x;
    int c = (int)((idx * 4 / N_) % CO_);
    float4 v = ((const float4*)g_h2)[idx];
    float sc = g_scale2[c], sh = g_shift2[c];
    v.x = fmaxf(fmaf(sc, v.x, sh), 0.f);
    v.y = fmaxf(fmaf(sc, v.y, sh), 0.f);
    v.z = fmaxf(fmaf(sc, v.z, sh), 0.f);
    v.w = fmaxf(fmaf(sc, v.w, sh), 0.f);
    ((float4*)out)[idx] = v;
}

// ---------------- launch ----------------------------------------------------------
extern "C" void kernel_launch(void* const* d_in, const int* in_sizes, int n_in,
                              void* d_out, int out_size) {
    const float* unknown      = (const float*)d_in[0];
    const float* known        = (const float*)d_in[1];
    const float* unknow_feats = (const float*)d_in[2];
    const float* known_feats  = (const float*)d_in[3];
    const float* W1 = (const float*)d_in[4];
    const float* g1 = (const float*)d_in[5];
    const float* b1 = (const float*)d_in[6];
    const float* W2 = (const float*)d_in[7];
    const float* g2 = (const float*)d_in[8];
    const float* b2 = (const float*)d_in[9];
    float* out = (float*)d_out;

    static bool attr_done = false;
    if (!attr_done) {
        cudaFuncSetAttribute(mma_gemm_kernel<0>, cudaFuncAttributeMaxDynamicSharedMemorySize, SMEM_TOTAL);
        cudaFuncSetAttribute(mma_gemm_kernel<1>, cudaFuncAttributeMaxDynamicSharedMemorySize, SMEM_TOTAL);
        attr_done = true;
    }

    __half* w1img; cudaGetSymbolAddress((void**)&w1img, g_w1img);
    __half* w2img; cudaGetSymbolAddress((void**)&w2img, g_w2img);
    {
        int tot1 = 16 * 256 * ROWE;
        wsplit_img_kernel<<<(tot1 + 255) / 256, 256>>>(W1, 512, tot1, w1img, 1);
        int tot2 = 8 * 256 * ROWE;
        wsplit_img_kernel<<<(tot2 + 255) / 256, 256>>>(W2, 256, tot2, w2img, 0);
    }
    knn_part_kernel<<<dim3(N_ / 128, 4, B_), 128>>>(unknown, known);
    knn_merge_kernel<<<dim3(N_ / 128, B_), 128>>>();
    interp_kernel<<<dim3(C2_ / 8, B_), 256>>>(known_feats);

    dim3 ggrid(CO_ / TM, N_ / TN, B_);
    mma_gemm_kernel<0><<<ggrid, 256, SMEM_TOTAL>>>(unknow_feats);
    finalize_kernel<0><<<1, 256>>>(g1, b1);
    mma_gemm_kernel<1><<<ggrid, 256, SMEM_TOTAL>>>(nullptr);
    finalize_kernel<1><<<1, 256>>>(g2, b2);
    apply_kernel<<<(size_t)B_ * CO_ * (N_ / 4) / 256, 256>>>(out);
}